// round 1
// baseline (speedup 1.0000x reference)
#include <cuda_runtime.h>

#define B_  2
#define C_  512
#define N_  2048
#define H_  8
#define DK_ 64
#define BH_ (B_*H_)

#define QT  16
#define KC  256
#define KPAD 65
#define VPAD 66

// Scratch (allocation-free rule: __device__ globals)
__device__ float g_q[BH_*N_*DK_];
__device__ float g_k[BH_*N_*DK_];
__device__ float g_v[BH_*N_*DK_];
__device__ float g_o[BH_*N_*DK_];

// ---------------------------------------------------------------------------
// Kernel 1: fused QKV projection.  Y[b,n,o] = sum_c x[b,c,n]*Wcat[o,c] + bcat[o]
// Tiled SGEMM: 64(n) x 64(o) x 16(c) tiles, 256 threads, 4x4 microtile.
// Writes directly into per-head layout g_{q,k,v}[((b*H+h)*N + n)*64 + d].
// ---------------------------------------------------------------------------
__global__ __launch_bounds__(256) void qkv_kernel(
    const float* __restrict__ x,
    const float* __restrict__ Wq, const float* __restrict__ bq,
    const float* __restrict__ Wk, const float* __restrict__ bk,
    const float* __restrict__ Wv, const float* __restrict__ bv)
{
    __shared__ float As[16][64];   // [c][n]
    __shared__ float Bs[16][65];   // [c][o]  (pad 65: conflict-free stores/loads)

    const int tid = threadIdx.x;
    const int ot  = blockIdx.x;          // 0..23  (o tiles of 64 over 1536)
    const int nt  = blockIdx.y;          // 0..31
    const int b   = blockIdx.z;

    const int o0    = ot * 64;
    const int mat   = o0 / 512;          // 0=Q 1=K 2=V
    const int orow0 = o0 % 512;
    const float* W    = (mat == 0) ? Wq : (mat == 1) ? Wk : Wv;
    const float* bias = (mat == 0) ? bq : (mat == 1) ? bk : bv;
    float*       dst  = (mat == 0) ? g_q : (mat == 1) ? g_k : g_v;
    const int n0 = nt * 64;

    const int tn = tid >> 4;   // 0..15 (n group)
    const int to = tid & 15;   // 0..15 (o group)

    float acc[4][4];
    #pragma unroll
    for (int i = 0; i < 4; i++)
        #pragma unroll
        for (int j = 0; j < 4; j++) acc[i][j] = 0.f;

    for (int kt = 0; kt < 32; kt++) {
        const int c0 = kt * 16;
        #pragma unroll
        for (int t = 0; t < 4; t++) {
            int idx = tid + t * 256;
            int kk = idx >> 6, ni = idx & 63;
            As[kk][ni] = x[(b * C_ + c0 + kk) * N_ + n0 + ni];
        }
        #pragma unroll
        for (int t = 0; t < 4; t++) {
            int idx = tid + t * 256;
            int kk = idx & 15, oi = idx >> 4;
            Bs[kk][oi] = W[(orow0 + oi) * C_ + c0 + kk];
        }
        __syncthreads();
        #pragma unroll
        for (int kk = 0; kk < 16; kk++) {
            float a[4], bb[4];
            #pragma unroll
            for (int i = 0; i < 4; i++) a[i]  = As[kk][tn + 16 * i];
            #pragma unroll
            for (int j = 0; j < 4; j++) bb[j] = Bs[kk][to + 16 * j];
            #pragma unroll
            for (int i = 0; i < 4; i++)
                #pragma unroll
                for (int j = 0; j < 4; j++)
                    acc[i][j] = fmaf(a[i], bb[j], acc[i][j]);
        }
        __syncthreads();
    }

    #pragma unroll
    for (int j = 0; j < 4; j++) {
        int o = orow0 + to + 16 * j;
        float bval = bias[o];
        int h = o >> 6, d = o & 63;
        #pragma unroll
        for (int i = 0; i < 4; i++) {
            int n = n0 + tn + 16 * i;
            dst[((b * H_ + h) * N_ + n) * DK_ + d] = acc[i][j] + bval;
        }
    }
}

// ---------------------------------------------------------------------------
// Kernel 2: fused attention with exact 1.5-entmax (bisection for tau).
// One CTA per (bh, 16-query tile).  512 threads = 16 warps; warp w owns row w.
//   Phase 1: z = (q.k / sqrt(64)) / 2 into SMEM (16 x 2048), K staged in chunks
//   Phase 2: per-warp: z row into registers, warp max, 26 bisection iters,
//            write p = clip(z - tau)^2 back in place
//   Phase 3: o = p @ V with V staged in SMEM chunks, broadcast p reads
// ---------------------------------------------------------------------------
__global__ __launch_bounds__(512, 1) void attn_kernel()
{
    extern __shared__ float smem[];
    float* Es  = smem;               // QT * N_          (131072 B)
    float* Qs  = Es + QT * N_;       // QT * 64          (4096 B)
    float* KVs = Qs + QT * DK_;      // KC * VPAD        (67584 B)

    const int tid = threadIdx.x;
    const int bh  = blockIdx.y;
    const int q0  = blockIdx.x * QT;

    const float* qptr = g_q + (bh * N_ + q0) * DK_;
    const float* kptr = g_k + bh * N_ * DK_;
    const float* vptr = g_v + bh * N_ * DK_;

    // load Q tile (row-major [qi][d], contiguous)
    #pragma unroll
    for (int t = 0; t < 2; t++) {
        int idx = tid + t * 512;
        Qs[idx] = qptr[idx];
    }
    __syncthreads();

    // ---- Phase 1: energies -> Es (pre-scaled by 1/16 = (1/sqrt(64))/2) ----
    const int qg = tid >> 6;   // 0..7  (2 q rows each)
    const int kg = tid & 63;   // 0..63 (4 k cols each, strided by 64)
    const float scale = 1.f / 16.f;

    for (int kc = 0; kc < N_ / KC; kc++) {
        #pragma unroll
        for (int t = 0; t < (KC * DK_) / 512; t++) {
            int idx = tid + t * 512;
            int r = idx >> 6, cl = idx & 63;
            KVs[r * KPAD + cl] = kptr[(kc * KC + r) * DK_ + cl];
        }
        __syncthreads();

        float acc[2][4];
        #pragma unroll
        for (int ii = 0; ii < 2; ii++)
            #pragma unroll
            for (int jj = 0; jj < 4; jj++) acc[ii][jj] = 0.f;

        #pragma unroll 16
        for (int d = 0; d < 64; d++) {
            float a0 = Qs[(2 * qg)     * 64 + d];
            float a1 = Qs[(2 * qg + 1) * 64 + d];
            #pragma unroll
            for (int jj = 0; jj < 4; jj++) {
                float bv = KVs[(kg + 64 * jj) * KPAD + d];
                acc[0][jj] = fmaf(a0, bv, acc[0][jj]);
                acc[1][jj] = fmaf(a1, bv, acc[1][jj]);
            }
        }
        #pragma unroll
        for (int ii = 0; ii < 2; ii++)
            #pragma unroll
            for (int jj = 0; jj < 4; jj++)
                Es[(2 * qg + ii) * N_ + kc * KC + kg + 64 * jj] = acc[ii][jj] * scale;
        __syncthreads();
    }

    // ---- Phase 2: entmax15 per row (warp w -> row w), tau by bisection ----
    const int w = tid >> 5, l = tid & 31;
    float* erow = Es + w * N_;

    float z[64];
    #pragma unroll
    for (int j = 0; j < 64; j++) z[j] = erow[l + 32 * j];

    float m = -1e30f;
    #pragma unroll
    for (int j = 0; j < 64; j++) m = fmaxf(m, z[j]);
    #pragma unroll
    for (int off = 16; off; off >>= 1)
        m = fmaxf(m, __shfl_xor_sync(0xffffffffu, m, off));
    #pragma unroll
    for (int j = 0; j < 64; j++) z[j] -= m;

    // f(tau) = sum clip(z - tau)^2 is decreasing; tau* in [-1, 0]
    float lo = -1.f, hi = 0.f;
    for (int it = 0; it < 26; it++) {
        float mid = 0.5f * (lo + hi);
        float s = 0.f;
        #pragma unroll
        for (int j = 0; j < 64; j++) {
            float t = fmaxf(z[j] - mid, 0.f);
            s = fmaf(t, t, s);
        }
        #pragma unroll
        for (int off = 16; off; off >>= 1)
            s += __shfl_xor_sync(0xffffffffu, s, off);
        bool ge = (s >= 1.f);
        lo = ge ? mid : lo;
        hi = ge ? hi : mid;
    }
    float tau = 0.5f * (lo + hi);
    #pragma unroll
    for (int j = 0; j < 64; j++) {
        float t = fmaxf(z[j] - tau, 0.f);
        erow[l + 32 * j] = t * t;   // Es now holds p
    }
    __syncthreads();

    // ---- Phase 3: o = p @ V, V staged in SMEM, broadcast p ----
    float2 acc2 = make_float2(0.f, 0.f);
    for (int vc = 0; vc < N_ / KC; vc++) {
        if (vc > 0) __syncthreads();   // all warps done with previous V chunk
        #pragma unroll
        for (int t = 0; t < (KC * DK_) / 512; t++) {
            int idx = tid + t * 512;
            int r = idx >> 6, cl = idx & 63;
            KVs[r * VPAD + cl] = vptr[(vc * KC + r) * DK_ + cl];
        }
        __syncthreads();

        const float* prow = erow + vc * KC;
        #pragma unroll 8
        for (int k = 0; k < KC; k++) {
            float p = prow[k];                 // broadcast LDS, warp-uniform
            if (p != 0.f) {                    // entmax sparsity: skip zeros
                float2 v = *reinterpret_cast<const float2*>(&KVs[k * VPAD + 2 * l]);
                acc2.x = fmaf(p, v.x, acc2.x);
                acc2.y = fmaf(p, v.y, acc2.y);
            }
        }
    }

    float* orow = g_o + (bh * N_ + q0 + w) * DK_;
    reinterpret_cast<float2*>(orow)[l] = acc2;
}

// ---------------------------------------------------------------------------
// Kernel 3: residual + LayerNorm (unbiased std, eps added to std).
// One CTA per (b, n); 128 threads x 4 channels.
// ---------------------------------------------------------------------------
__global__ __launch_bounds__(128) void ln_kernel(
    const float* __restrict__ x, const float* __restrict__ a2,
    const float* __restrict__ b2, float* __restrict__ out)
{
    const int bn = blockIdx.x;
    const int b = bn / N_, n = bn % N_;
    const int t = threadIdx.x;

    float v[4];
    #pragma unroll
    for (int i = 0; i < 4; i++) {
        int c = t + 128 * i;
        int h = c >> 6, d = c & 63;
        v[i] = g_o[((b * H_ + h) * N_ + n) * DK_ + d];
    }
    float s  = v[0] + v[1] + v[2] + v[3];
    float ss = v[0]*v[0] + v[1]*v[1] + v[2]*v[2] + v[3]*v[3];

    __shared__ float rs[4], rss[4];
    #pragma unroll
    for (int off = 16; off; off >>= 1) {
        s  += __shfl_xor_sync(0xffffffffu, s, off);
        ss += __shfl_xor_sync(0xffffffffu, ss, off);
    }
    int wi = t >> 5, li = t & 31;
    if (li == 0) { rs[wi] = s; rss[wi] = ss; }
    __syncthreads();
    s  = rs[0] + rs[1] + rs[2] + rs[3];
    ss = rss[0] + rss[1] + rss[2] + rss[3];

    float mean = s * (1.f / 512.f);
    float var  = (ss - 512.f * mean * mean) * (1.f / 511.f);
    var = fmaxf(var, 0.f);
    float inv = 1.f / (sqrtf(var) + 1e-6f);

    #pragma unroll
    for (int i = 0; i < 4; i++) {
        int c = t + 128 * i;
        float res = x[(b * C_ + c) * N_ + n];
        out[bn * C_ + c] = a2[c] * (v[i] - mean) * inv + b2[c] + res;
    }
}

// ---------------------------------------------------------------------------
extern "C" void kernel_launch(void* const* d_in, const int* in_sizes, int n_in,
                              void* d_out, int out_size)
{
    const float* x  = (const float*)d_in[0];
    const float* Wq = (const float*)d_in[1];
    const float* bq = (const float*)d_in[2];
    const float* Wk = (const float*)d_in[3];
    const float* bk = (const float*)d_in[4];
    const float* Wv = (const float*)d_in[5];
    const float* bv = (const float*)d_in[6];
    const float* a2 = (const float*)d_in[7];
    const float* b2 = (const float*)d_in[8];
    float* out = (float*)d_out;

    dim3 g1(24, 32, 2);
    qkv_kernel<<<g1, 256>>>(x, Wq, bq, Wk, bk, Wv, bv);

    const int smem_bytes = (QT * N_ + QT * DK_ + KC * VPAD) * 4;
    cudaFuncSetAttribute(attn_kernel, cudaFuncAttributeMaxDynamicSharedMemorySize,
                         smem_bytes);
    dim3 g2(N_ / QT, BH_);
    attn_kernel<<<g2, 512, smem_bytes>>>();

    ln_kernel<<<B_ * N_, 128>>>(x, a2, b2, out);
}